// round 4
// baseline (speedup 1.0000x reference)
#include <cuda_runtime.h>
#include <math.h>

// Problem shape (fixed by the dataset instance)
#define FR  128      // frames = B*T
#define NP  300      // predictions per frame
#define NC  2        // classes
#define MT  32       // targets per frame
#define KD  512      // id classes

#define W_CLS  2.0f
#define W_BBOX 5.0f
#define W_GIOU 2.0f

__device__ double g_partial[FR * 3];   // per-frame {sum_l1, sum_giou, sum_nll}

struct SMem {
    // doubles first for alignment
    double u[MT + 1];
    double v[NP + 1];
    double minv[NP + 1];
    double s_l1[MT];
    double s_g[MT];
    double s_nll[MT];
    float  cost[MT * NP];     // cost[t*NP + j]  (rows = targets, cols = preds)
    float  pcx[NP * 4];       // pred boxes cxcywh
    float  pxy[NP * 5];       // pred x0,y0,x1,y1,area
    float  prob[NP * NC];     // softmax probs
    float  tcx[MT * 4];       // target boxes cxcywh
    float  txy[MT * 5];       // target x0,y0,x1,y1,area
    int    tlab[MT];
    int    p[NP + 1];
    int    way[NP + 1];
    int    used[NP + 1];
    int    col4row[MT];
};

__device__ __forceinline__ float giou_f(
    float ax0, float ay0, float ax1, float ay1, float aarea,
    float bx0, float by0, float bx1, float by1, float barea)
{
    float ltx = fmaxf(ax0, bx0), lty = fmaxf(ay0, by0);
    float rbx = fminf(ax1, bx1), rby = fminf(ay1, by1);
    float w = fmaxf(rbx - ltx, 0.0f), h = fmaxf(rby - lty, 0.0f);
    float inter = w * h;
    float uni = aarea + barea - inter;
    float iou = inter / uni;
    float LTx = fminf(ax0, bx0), LTy = fminf(ay0, by0);
    float RBx = fmaxf(ax1, bx1), RBy = fmaxf(ay1, by1);
    float W = fmaxf(RBx - LTx, 0.0f), H = fmaxf(RBy - LTy, 0.0f);
    float ac = W * H;
    return iou - (ac - uni) / ac;
}

__global__ __launch_bounds__(128, 1)
void motip_frame_kernel(const float* __restrict__ pl,   // [FR,NP,NC]
                        const float* __restrict__ pb,   // [FR,NP,4]
                        const float* __restrict__ il,   // [FR,NP,KD]
                        const int*   __restrict__ tlabels, // [FR,MT]
                        const float* __restrict__ tb,   // [FR,MT,4]
                        const int*   __restrict__ tids) // [FR,MT]
{
    extern __shared__ char sraw[];
    SMem& s = *reinterpret_cast<SMem*>(sraw);
    const int f    = blockIdx.x;
    const int tid  = threadIdx.x;
    const int lane = tid & 31;
    const int wid  = tid >> 5;

    // ---------------- Phase 1: load preds / targets, softmax, xyxy ----------
    for (int j = tid; j < NP; j += 128) {
        const float* bp = pb + ((size_t)f * NP + j) * 4;
        float cx = bp[0], cy = bp[1], w = bp[2], h = bp[3];
        s.pcx[j * 4 + 0] = cx; s.pcx[j * 4 + 1] = cy;
        s.pcx[j * 4 + 2] = w;  s.pcx[j * 4 + 3] = h;
        float x0 = cx - 0.5f * w, y0 = cy - 0.5f * h;
        float x1 = cx + 0.5f * w, y1 = cy + 0.5f * h;
        s.pxy[j * 5 + 0] = x0; s.pxy[j * 5 + 1] = y0;
        s.pxy[j * 5 + 2] = x1; s.pxy[j * 5 + 3] = y1;
        s.pxy[j * 5 + 4] = (x1 - x0) * (y1 - y0);
        const float* lp = pl + ((size_t)f * NP + j) * NC;
        float l0 = lp[0], l1 = lp[1];
        float mx = fmaxf(l0, l1);
        float e0 = expf(l0 - mx), e1 = expf(l1 - mx);
        float inv = 1.0f / (e0 + e1);
        s.prob[j * 2 + 0] = e0 * inv;
        s.prob[j * 2 + 1] = e1 * inv;
    }
    if (tid < MT) {
        const float* bp = tb + ((size_t)f * MT + tid) * 4;
        float cx = bp[0], cy = bp[1], w = bp[2], h = bp[3];
        s.tcx[tid * 4 + 0] = cx; s.tcx[tid * 4 + 1] = cy;
        s.tcx[tid * 4 + 2] = w;  s.tcx[tid * 4 + 3] = h;
        float x0 = cx - 0.5f * w, y0 = cy - 0.5f * h;
        float x1 = cx + 0.5f * w, y1 = cy + 0.5f * h;
        s.txy[tid * 5 + 0] = x0; s.txy[tid * 5 + 1] = y0;
        s.txy[tid * 5 + 2] = x1; s.txy[tid * 5 + 3] = y1;
        s.txy[tid * 5 + 4] = (x1 - x0) * (y1 - y0);
        s.tlab[tid] = tlabels[f * MT + tid];
    }
    __syncthreads();

    // ---------------- Phase 2: cost matrix [MT x NP] ------------------------
    for (int e = tid; e < MT * NP; e += 128) {
        int t = e / NP;
        int j = e - t * NP;
        float l1s = fabsf(s.pcx[j*4+0] - s.tcx[t*4+0])
                  + fabsf(s.pcx[j*4+1] - s.tcx[t*4+1])
                  + fabsf(s.pcx[j*4+2] - s.tcx[t*4+2])
                  + fabsf(s.pcx[j*4+3] - s.tcx[t*4+3]);
        float g = giou_f(s.pxy[j*5+0], s.pxy[j*5+1], s.pxy[j*5+2], s.pxy[j*5+3], s.pxy[j*5+4],
                         s.txy[t*5+0], s.txy[t*5+1], s.txy[t*5+2], s.txy[t*5+3], s.txy[t*5+4]);
        float cc = -s.prob[j * 2 + s.tlab[t]];
        s.cost[t * NP + j] = W_CLS * cc + W_BBOX * l1s + W_GIOU * (-g);
    }
    __syncthreads();

    // ---------------- Phase 3: JV Hungarian (warp 0 only) -------------------
    if (wid == 0) {
        const double INF = 1e300;
        for (int j = lane; j <= NP; j += 32) { s.v[j] = 0.0; s.p[j] = 0; }
        for (int r = lane; r <= MT; r += 32) s.u[r] = 0.0;
        __syncwarp();

        for (int i = 1; i <= MT; i++) {
            if (lane == 0) s.p[0] = i;
            for (int j = lane; j <= NP; j += 32) { s.minv[j] = INF; s.used[j] = 0; }
            __syncwarp();
            int j0 = 0;
            for (;;) {
                if (lane == 0) s.used[j0] = 1;
                __syncwarp();
                int i0 = s.p[j0];
                double ui0 = s.u[i0];
                const float* crow = &s.cost[(i0 - 1) * NP];
                double best = INF;
                int bestj = NP + 1;
                for (int j = 1 + lane; j <= NP; j += 32) {
                    if (!s.used[j]) {
                        double cur = (double)crow[j - 1] - ui0 - s.v[j];
                        if (cur < s.minv[j]) { s.minv[j] = cur; s.way[j] = j0; }
                        double mj = s.minv[j];
                        if (mj < best) { best = mj; bestj = j; }
                    }
                }
                // warp argmin, tie-break smallest j (numpy argmin semantics)
                for (int off = 16; off; off >>= 1) {
                    double ob = __shfl_down_sync(0xffffffffu, best, off);
                    int    oj = __shfl_down_sync(0xffffffffu, bestj, off);
                    if (ob < best || (ob == best && oj < bestj)) { best = ob; bestj = oj; }
                }
                best  = __shfl_sync(0xffffffffu, best, 0);
                bestj = __shfl_sync(0xffffffffu, bestj, 0);
                double delta = best;
                int j1 = bestj;
                for (int j = lane; j <= NP; j += 32) {
                    if (s.used[j]) { s.u[s.p[j]] += delta; s.v[j] -= delta; }
                    else            s.minv[j] -= delta;
                }
                __syncwarp();
                j0 = j1;
                if (s.p[j0] == 0) break;
            }
            if (lane == 0) {
                int jj = j0;
                while (jj) { int jn = s.way[jj]; s.p[jj] = s.p[jn]; jj = jn; }
            }
            __syncwarp();
        }
        for (int j = 1 + lane; j <= NP; j += 32)
            if (s.p[j] > 0) s.col4row[s.p[j] - 1] = j - 1;
        __syncwarp();
    }
    __syncthreads();

    // ---------------- Phase 4: losses ---------------------------------------
    if (tid < MT) {
        int k = s.col4row[tid];
        float l1s = fabsf(s.pcx[k*4+0] - s.tcx[tid*4+0])
                  + fabsf(s.pcx[k*4+1] - s.tcx[tid*4+1])
                  + fabsf(s.pcx[k*4+2] - s.tcx[tid*4+2])
                  + fabsf(s.pcx[k*4+3] - s.tcx[tid*4+3]);
        s.s_l1[tid] = (double)l1s;
        float g = giou_f(s.pxy[k*5+0], s.pxy[k*5+1], s.pxy[k*5+2], s.pxy[k*5+3], s.pxy[k*5+4],
                         s.txy[tid*5+0], s.txy[tid*5+1], s.txy[tid*5+2], s.txy[tid*5+3], s.txy[tid*5+4]);
        s.s_g[tid] = (double)g;
    }

    // ID cross-entropy: one warp per 8 targets, 512-wide logsumexp
    for (int t = wid * 8; t < wid * 8 + 8; t++) {
        int k = s.col4row[t];
        const float* row = il + ((size_t)f * NP + k) * KD;
        float vals[16];
        #pragma unroll
        for (int c = 0; c < 16; c++) vals[c] = row[lane + 32 * c];
        float mx = vals[0];
        #pragma unroll
        for (int c = 1; c < 16; c++) mx = fmaxf(mx, vals[c]);
        for (int off = 16; off; off >>= 1)
            mx = fmaxf(mx, __shfl_xor_sync(0xffffffffu, mx, off));
        float se = 0.0f;
        #pragma unroll
        for (int c = 0; c < 16; c++) se += expf(vals[c] - mx);
        for (int off = 16; off; off >>= 1)
            se += __shfl_xor_sync(0xffffffffu, se, off);
        if (lane == 0) {
            int tg = tids[f * MT + t];
            float lse = mx + logf(se);
            s.s_nll[t] = (double)(lse - row[tg]);
        }
    }
    __syncthreads();

    if (tid == 0) {
        double a = 0.0, b = 0.0, c = 0.0;
        for (int t = 0; t < MT; t++) { a += s.s_l1[t]; b += s.s_g[t]; c += s.s_nll[t]; }
        g_partial[f * 3 + 0] = a;
        g_partial[f * 3 + 1] = b;
        g_partial[f * 3 + 2] = c;
    }
}

__global__ void motip_finalize_kernel(float* __restrict__ out) {
    if (threadIdx.x == 0) {
        double sl = 0.0, sg = 0.0, sn = 0.0;
        for (int f = 0; f < FR; f++) {
            sl += g_partial[f * 3 + 0];
            sg += g_partial[f * 3 + 1];
            sn += g_partial[f * 3 + 2];
        }
        double loss_l1   = sl / (double)(FR * MT * 4);
        double loss_giou = 1.0 - sg / (double)(FR * MT);
        double loss_id   = sn / (double)(FR * MT);
        double loss = 5.0 * loss_l1 + 2.0 * loss_giou + 1.0 * loss_id; // cls stub = 0
        out[0] = (float)loss;
        out[1] = 0.0f;
        out[2] = (float)loss_l1;
        out[3] = (float)loss_giou;
        out[4] = (float)loss_id;
    }
}

extern "C" void kernel_launch(void* const* d_in, const int* in_sizes, int n_in,
                              void* d_out, int out_size)
{
    const float* pl  = (const float*)d_in[0];
    const float* pb  = (const float*)d_in[1];
    const float* il  = (const float*)d_in[2];
    const int*   tl  = (const int*)  d_in[3];
    const float* tb  = (const float*)d_in[4];
    const int*   tid = (const int*)  d_in[5];

    size_t smem = sizeof(SMem);
    cudaFuncSetAttribute(motip_frame_kernel,
                         cudaFuncAttributeMaxDynamicSharedMemorySize, (int)smem);
    motip_frame_kernel<<<FR, 128, smem>>>(pl, pb, il, tl, tb, tid);
    motip_finalize_kernel<<<1, 32>>>((float*)d_out);
}

// round 7
// speedup vs baseline: 2.1049x; 2.1049x over previous
#include <cuda_runtime.h>
#include <math.h>
#include <float.h>

// Problem shape (fixed by the dataset instance)
#define FR  128      // frames = B*T
#define NP  300      // predictions per frame
#define NC  2        // classes
#define MT  32       // targets per frame
#define KD  512      // id classes
#define NL  10       // register slots per lane for columns (ceil(300/32))

#define W_CLS  2.0f
#define W_BBOX 5.0f
#define W_GIOU 2.0f

__device__ double   g_partial[FR * 3];   // per-frame {sum_l1, sum_giou, sum_nll}
__device__ unsigned g_done;              // zero-initialized at module load; reset by last CTA

struct SMem {
    double s_l1[MT];
    double s_g[MT];
    double s_nll[MT];
    float  cost[MT * NP];     // cost[t*NP + j]  (rows = targets, cols = preds)
    float  pcx[NP * 4];       // pred boxes cxcywh
    float  pxy[NP * 5];       // pred x0,y0,x1,y1,area
    float  prob[NP * NC];     // softmax probs
    float  tcx[MT * 4];       // target boxes cxcywh
    float  txy[MT * 5];       // target x0,y0,x1,y1,area
    int    tlab[MT];
    int    col4row[MT];
    int    lastflag;
};

__device__ __forceinline__ float giou_f(
    float ax0, float ay0, float ax1, float ay1, float aarea,
    float bx0, float by0, float bx1, float by1, float barea)
{
    float ltx = fmaxf(ax0, bx0), lty = fmaxf(ay0, by0);
    float rbx = fminf(ax1, bx1), rby = fminf(ay1, by1);
    float w = fmaxf(rbx - ltx, 0.0f), h = fmaxf(rby - lty, 0.0f);
    float inter = w * h;
    float uni = aarea + barea - inter;
    float iou = inter / uni;
    float LTx = fminf(ax0, bx0), LTy = fminf(ay0, by0);
    float RBx = fmaxf(ax1, bx1), RBy = fmaxf(ay1, by1);
    float W = fmaxf(RBx - LTx, 0.0f), H = fmaxf(RBy - LTy, 0.0f);
    float ac = W * H;
    return iou - (ac - uni) / ac;
}

// Unrolled dynamic-uniform-index selects over small register arrays.
__device__ __forceinline__ float sel10f(const float* a, int s) {
    float r = a[0];
    #pragma unroll
    for (int k = 1; k < NL; k++) if (s == k) r = a[k];
    return r;
}
__device__ __forceinline__ int sel10i(const int* a, int s) {
    int r = a[0];
    #pragma unroll
    for (int k = 1; k < NL; k++) if (s == k) r = a[k];
    return r;
}
__device__ __forceinline__ void set10i(int* a, int s, int v) {
    #pragma unroll
    for (int k = 0; k < NL; k++) if (s == k) a[k] = v;
}

__global__ __launch_bounds__(128, 1)
void motip_frame_kernel(const float* __restrict__ pl,      // [FR,NP,NC]
                        const float* __restrict__ pb,      // [FR,NP,4]
                        const float* __restrict__ il,      // [FR,NP,KD]
                        const int*   __restrict__ tlabels, // [FR,MT]
                        const float* __restrict__ tb,      // [FR,MT,4]
                        const int*   __restrict__ tids,    // [FR,MT]
                        float*       __restrict__ out)     // [5]
{
    extern __shared__ char sraw[];
    SMem& s = *reinterpret_cast<SMem*>(sraw);
    const int f    = blockIdx.x;
    const int tid  = threadIdx.x;
    const int lane = tid & 31;
    const int wid  = tid >> 5;
    const unsigned FULL = 0xffffffffu;

    // ---------------- Phase 1: load preds / targets, softmax, xyxy ----------
    for (int j = tid; j < NP; j += 128) {
        const float* bp = pb + ((size_t)f * NP + j) * 4;
        float cx = bp[0], cy = bp[1], w = bp[2], h = bp[3];
        s.pcx[j * 4 + 0] = cx; s.pcx[j * 4 + 1] = cy;
        s.pcx[j * 4 + 2] = w;  s.pcx[j * 4 + 3] = h;
        float x0 = cx - 0.5f * w, y0 = cy - 0.5f * h;
        float x1 = cx + 0.5f * w, y1 = cy + 0.5f * h;
        s.pxy[j * 5 + 0] = x0; s.pxy[j * 5 + 1] = y0;
        s.pxy[j * 5 + 2] = x1; s.pxy[j * 5 + 3] = y1;
        s.pxy[j * 5 + 4] = (x1 - x0) * (y1 - y0);
        const float* lp = pl + ((size_t)f * NP + j) * NC;
        float l0 = lp[0], l1 = lp[1];
        float mx = fmaxf(l0, l1);
        float e0 = expf(l0 - mx), e1 = expf(l1 - mx);
        float inv = 1.0f / (e0 + e1);
        s.prob[j * 2 + 0] = e0 * inv;
        s.prob[j * 2 + 1] = e1 * inv;
    }
    if (tid < MT) {
        const float* bp = tb + ((size_t)f * MT + tid) * 4;
        float cx = bp[0], cy = bp[1], w = bp[2], h = bp[3];
        s.tcx[tid * 4 + 0] = cx; s.tcx[tid * 4 + 1] = cy;
        s.tcx[tid * 4 + 2] = w;  s.tcx[tid * 4 + 3] = h;
        float x0 = cx - 0.5f * w, y0 = cy - 0.5f * h;
        float x1 = cx + 0.5f * w, y1 = cy + 0.5f * h;
        s.txy[tid * 5 + 0] = x0; s.txy[tid * 5 + 1] = y0;
        s.txy[tid * 5 + 2] = x1; s.txy[tid * 5 + 3] = y1;
        s.txy[tid * 5 + 4] = (x1 - x0) * (y1 - y0);
        s.tlab[tid] = tlabels[f * MT + tid];
    }
    __syncthreads();

    // ---------------- Phase 2: cost matrix [MT x NP] ------------------------
    for (int e = tid; e < MT * NP; e += 128) {
        int t = e / NP;
        int j = e - t * NP;
        float l1s = fabsf(s.pcx[j*4+0] - s.tcx[t*4+0])
                  + fabsf(s.pcx[j*4+1] - s.tcx[t*4+1])
                  + fabsf(s.pcx[j*4+2] - s.tcx[t*4+2])
                  + fabsf(s.pcx[j*4+3] - s.tcx[t*4+3]);
        float g = giou_f(s.pxy[j*5+0], s.pxy[j*5+1], s.pxy[j*5+2], s.pxy[j*5+3], s.pxy[j*5+4],
                         s.txy[t*5+0], s.txy[t*5+1], s.txy[t*5+2], s.txy[t*5+3], s.txy[t*5+4]);
        float cc = -s.prob[j * 2 + s.tlab[t]];
        s.cost[t * NP + j] = W_CLS * cc + W_BBOX * l1s + W_GIOU * (-g);
    }
    __syncthreads();

    // ---------------- Phase 3: Hungarian, register-resident float JV --------
    // scipy rectangular_lsap formulation: static duals during the path,
    // shortest-path costs relaxed each step, argmin over unscanned columns.
    // Lane L owns columns j = k*32 + L (k = 0..NL-1, valid while j < NP).
    if (wid == 0) {
        const float INF = FLT_MAX;
        float v_[NL], spc[NL];
        int   pathr[NL], r4c[NL];
        unsigned invmask = 0;
        #pragma unroll
        for (int k = 0; k < NL; k++) {
            int j = k * 32 + lane;
            if (j >= NP) invmask |= 1u << k;
            v_[k] = 0.0f; r4c[k] = -1; pathr[k] = 0;
        }
        float u_own  = 0.0f;   // lane r owns u[r]
        int   c4r_own = -1;    // lane r owns col4row[r]

        for (int cur = 0; cur < MT; cur++) {
            unsigned SC = invmask;   // scanned-columns mask, per lane
            unsigned SR = 0;         // scanned-rows mask, uniform
            #pragma unroll
            for (int k = 0; k < NL; k++) spc[k] = INF;
            float minVal = 0.0f;
            int i = cur;
            int sink = -1;

            while (sink < 0) {
                SR |= 1u << i;
                float u_i = __shfl_sync(FULL, u_own, i);
                const float* crow = s.cost + i * NP + lane;
                float c_[NL];
                #pragma unroll
                for (int k = 0; k < NL; k++)
                    c_[k] = ((invmask >> k) & 1) ? 0.0f : crow[k * 32];

                float best = INF; int bestj = 1 << 20; int bestfree = 0;
                #pragma unroll
                for (int k = 0; k < NL; k++) {
                    if (!((SC >> k) & 1)) {
                        float r = minVal + c_[k] - u_i - v_[k];
                        if (r < spc[k]) { spc[k] = r; pathr[k] = i; }
                        float sv = spc[k];
                        int   fr = (r4c[k] < 0);
                        int   j  = k * 32 + lane;
                        bool better = (sv < best) ||
                                      (sv == best && ((fr && !bestfree) ||
                                                      (fr == bestfree && j < bestj)));
                        if (better) { best = sv; bestj = j; bestfree = fr; }
                    }
                }
                #pragma unroll
                for (int off = 16; off; off >>= 1) {
                    float ob = __shfl_down_sync(FULL, best, off);
                    int   oj = __shfl_down_sync(FULL, bestj, off);
                    int   of = __shfl_down_sync(FULL, bestfree, off);
                    bool better = (ob < best) ||
                                  (ob == best && ((of && !bestfree) ||
                                                  (of == bestfree && oj < bestj)));
                    if (better) { best = ob; bestj = oj; bestfree = of; }
                }
                best     = __shfl_sync(FULL, best, 0);
                bestj    = __shfl_sync(FULL, bestj, 0);
                bestfree = __shfl_sync(FULL, bestfree, 0);
                minVal = best;

                int owner = bestj & 31, slot = bestj >> 5;
                int r4cv = sel10i(r4c, slot);
                r4cv = __shfl_sync(FULL, r4cv, owner);
                if (lane == owner) SC |= 1u << slot;
                if (bestfree || r4cv < 0) sink = bestj;
                else                      i = r4cv;
            }

            // Dual updates (scipy order: before augmentation, old col4row)
            if (lane == cur) u_own += minVal;
            unsigned m = SR & ~(1u << cur);
            while (m) {
                int it = __ffs(m) - 1; m &= m - 1;
                int jcol = __shfl_sync(FULL, c4r_own, it);
                int slot2 = jcol >> 5, own2 = jcol & 31;
                float sv = sel10f(spc, slot2);
                sv = __shfl_sync(FULL, sv, own2);
                if (lane == it) u_own += minVal - sv;
            }
            #pragma unroll
            for (int k = 0; k < NL; k++) {
                if (((SC >> k) & 1) && !((invmask >> k) & 1))
                    v_[k] -= minVal - spc[k];
            }

            // Augment along the path
            int j = sink;
            for (;;) {
                int slot2 = j >> 5, own2 = j & 31;
                int pv = sel10i(pathr, slot2);
                pv = __shfl_sync(FULL, pv, own2);       // row that reached col j
                if (lane == own2) set10i(r4c, slot2, pv);
                int jn = __shfl_sync(FULL, c4r_own, pv);
                if (lane == pv) c4r_own = j;
                if (pv == cur) break;
                j = jn;
            }
        }
        s.col4row[lane] = c4r_own;
    }
    __syncthreads();

    // ---------------- Phase 4: losses ---------------------------------------
    if (tid < MT) {
        int k = s.col4row[tid];
        float l1s = fabsf(s.pcx[k*4+0] - s.tcx[tid*4+0])
                  + fabsf(s.pcx[k*4+1] - s.tcx[tid*4+1])
                  + fabsf(s.pcx[k*4+2] - s.tcx[tid*4+2])
                  + fabsf(s.pcx[k*4+3] - s.tcx[tid*4+3]);
        s.s_l1[tid] = (double)l1s;
        float g = giou_f(s.pxy[k*5+0], s.pxy[k*5+1], s.pxy[k*5+2], s.pxy[k*5+3], s.pxy[k*5+4],
                         s.txy[tid*5+0], s.txy[tid*5+1], s.txy[tid*5+2], s.txy[tid*5+3], s.txy[tid*5+4]);
        s.s_g[tid] = (double)g;
    }

    // ID cross-entropy: one warp per 8 targets, 512-wide logsumexp
    for (int t = wid * 8; t < wid * 8 + 8; t++) {
        int k = s.col4row[t];
        const float* row = il + ((size_t)f * NP + k) * KD;
        float vals[16];
        #pragma unroll
        for (int c = 0; c < 16; c++) vals[c] = row[lane + 32 * c];
        float mx = vals[0];
        #pragma unroll
        for (int c = 1; c < 16; c++) mx = fmaxf(mx, vals[c]);
        for (int off = 16; off; off >>= 1)
            mx = fmaxf(mx, __shfl_xor_sync(0xffffffffu, mx, off));
        float se = 0.0f;
        #pragma unroll
        for (int c = 0; c < 16; c++) se += expf(vals[c] - mx);
        for (int off = 16; off; off >>= 1)
            se += __shfl_xor_sync(0xffffffffu, se, off);
        if (lane == 0) {
            int tg = tids[f * MT + t];
            float lse = mx + logf(se);
            s.s_nll[t] = (double)(lse - row[tg]);
        }
    }
    __syncthreads();

    if (tid == 0) {
        double a = 0.0, b = 0.0, c = 0.0;
        for (int t = 0; t < MT; t++) { a += s.s_l1[t]; b += s.s_g[t]; c += s.s_nll[t]; }
        g_partial[f * 3 + 0] = a;
        g_partial[f * 3 + 1] = b;
        g_partial[f * 3 + 2] = c;
        __threadfence();
        unsigned t = atomicAdd(&g_done, 1u);
        s.lastflag = (t == FR - 1);
    }
    __syncthreads();

    // ---------------- Fused finalize: last CTA reduces all frames -----------
    if (s.lastflag && wid == 0) {
        double a = 0.0, b = 0.0, c = 0.0;
        for (int fr = lane; fr < FR; fr += 32) {
            a += __ldcg(&g_partial[fr * 3 + 0]);
            b += __ldcg(&g_partial[fr * 3 + 1]);
            c += __ldcg(&g_partial[fr * 3 + 2]);
        }
        #pragma unroll
        for (int off = 16; off; off >>= 1) {
            a += __shfl_down_sync(0xffffffffu, a, off);
            b += __shfl_down_sync(0xffffffffu, b, off);
            c += __shfl_down_sync(0xffffffffu, c, off);
        }
        if (lane == 0) {
            double loss_l1   = a / (double)(FR * MT * 4);
            double loss_giou = 1.0 - b / (double)(FR * MT);
            double loss_id   = c / (double)(FR * MT);
            double loss = 5.0 * loss_l1 + 2.0 * loss_giou + 1.0 * loss_id; // cls stub = 0
            out[0] = (float)loss;
            out[1] = 0.0f;
            out[2] = (float)loss_l1;
            out[3] = (float)loss_giou;
            out[4] = (float)loss_id;
            g_done = 0;   // reset for next graph replay
        }
    }
}

extern "C" void kernel_launch(void* const* d_in, const int* in_sizes, int n_in,
                              void* d_out, int out_size)
{
    const float* pl  = (const float*)d_in[0];
    const float* pb  = (const float*)d_in[1];
    const float* il  = (const float*)d_in[2];
    const int*   tl  = (const int*)  d_in[3];
    const float* tb  = (const float*)d_in[4];
    const int*   tid = (const int*)  d_in[5];

    size_t smem = sizeof(SMem);
    cudaFuncSetAttribute(motip_frame_kernel,
                         cudaFuncAttributeMaxDynamicSharedMemorySize, (int)smem);
    motip_frame_kernel<<<FR, 128, smem>>>(pl, pb, il, tl, tb, tid, (float*)d_out);
}

// round 12
// speedup vs baseline: 2.9545x; 1.4036x over previous
#include <cuda_runtime.h>
#include <math.h>
#include <float.h>

// Problem shape (fixed by the dataset instance)
#define FR  128      // frames = B*T
#define NP  300      // predictions per frame
#define NC  2        // classes
#define MT  32       // targets per frame
#define KD  512      // id classes
#define NL  10       // register slots per lane for columns (ceil(300/32))

#define W_CLS  2.0f
#define W_BBOX 5.0f
#define W_GIOU 2.0f

__device__ double   g_partial[FR * 3];   // per-frame {sum_l1, sum_giou, sum_nll}
__device__ unsigned g_done;              // zero-init at module load; reset by last CTA

struct SMem {
    double s_l1[MT];
    double s_g[MT];
    double s_nll[MT];
    float  cost[MT * NP];     // cost[t*NP + j]  (rows = targets, cols = preds)
    float  pcx[NP * 4];       // pred boxes cxcywh
    float  pxy[NP * 5];       // pred x0,y0,x1,y1,area
    float  prob[NP * NC];     // softmax probs
    float  tcx[MT * 4];       // target boxes cxcywh
    float  txy[MT * 5];       // target x0,y0,x1,y1,area
    int    tlab[MT];
    int    col4row[MT];
    int    lastflag;
};

__device__ __forceinline__ float giou_f(
    float ax0, float ay0, float ax1, float ay1, float aarea,
    float bx0, float by0, float bx1, float by1, float barea)
{
    float ltx = fmaxf(ax0, bx0), lty = fmaxf(ay0, by0);
    float rbx = fminf(ax1, bx1), rby = fminf(ay1, by1);
    float w = fmaxf(rbx - ltx, 0.0f), h = fmaxf(rby - lty, 0.0f);
    float inter = w * h;
    float uni = aarea + barea - inter;
    float iou = inter / uni;
    float LTx = fminf(ax0, bx0), LTy = fminf(ay0, by0);
    float RBx = fmaxf(ax1, bx1), RBy = fmaxf(ay1, by1);
    float W = fmaxf(RBx - LTx, 0.0f), H = fmaxf(RBy - LTy, 0.0f);
    float ac = W * H;
    return iou - (ac - uni) / ac;
}

// Unrolled dynamic-uniform-index selects over small register arrays.
__device__ __forceinline__ int sel10i(const int* a, int s) {
    int r = a[0];
    #pragma unroll
    for (int k = 1; k < NL; k++) if (s == k) r = a[k];
    return r;
}
__device__ __forceinline__ void set10i(int* a, int s, int v) {
    #pragma unroll
    for (int k = 0; k < NL; k++) if (s == k) a[k] = v;
}

// Order-preserving float <-> u32 maps (total order == float < on non-NaN,
// provided -0.0 is normalized to +0.0 before mapping)
__device__ __forceinline__ unsigned fmap(float f) {
    unsigned b = __float_as_uint(f);
    return (b & 0x80000000u) ? ~b : (b | 0x80000000u);
}
__device__ __forceinline__ float funmap(unsigned m) {
    unsigned b = (m & 0x80000000u) ? (m & 0x7FFFFFFFu) : ~m;
    return __uint_as_float(b);
}

__global__ __launch_bounds__(128, 1)
void motip_frame_kernel(const float* __restrict__ pl,      // [FR,NP,NC]
                        const float* __restrict__ pb,      // [FR,NP,4]
                        const float* __restrict__ il,      // [FR,NP,KD]
                        const int*   __restrict__ tlabels, // [FR,MT]
                        const float* __restrict__ tb,      // [FR,MT,4]
                        const int*   __restrict__ tids,    // [FR,MT]
                        float*       __restrict__ out)     // [5]
{
    extern __shared__ char sraw[];
    SMem& s = *reinterpret_cast<SMem*>(sraw);
    const int f    = blockIdx.x;
    const int tid  = threadIdx.x;
    const int lane = tid & 31;
    const int wid  = tid >> 5;
    const unsigned FULL = 0xffffffffu;

    // ---------------- Phase 1: load preds / targets, softmax, xyxy ----------
    for (int j = tid; j < NP; j += 128) {
        const float* bp = pb + ((size_t)f * NP + j) * 4;
        float cx = bp[0], cy = bp[1], w = bp[2], h = bp[3];
        s.pcx[j * 4 + 0] = cx; s.pcx[j * 4 + 1] = cy;
        s.pcx[j * 4 + 2] = w;  s.pcx[j * 4 + 3] = h;
        float x0 = cx - 0.5f * w, y0 = cy - 0.5f * h;
        float x1 = cx + 0.5f * w, y1 = cy + 0.5f * h;
        s.pxy[j * 5 + 0] = x0; s.pxy[j * 5 + 1] = y0;
        s.pxy[j * 5 + 2] = x1; s.pxy[j * 5 + 3] = y1;
        s.pxy[j * 5 + 4] = (x1 - x0) * (y1 - y0);
        const float* lp = pl + ((size_t)f * NP + j) * NC;
        float l0 = lp[0], l1 = lp[1];
        float mx = fmaxf(l0, l1);
        float e0 = expf(l0 - mx), e1 = expf(l1 - mx);
        float inv = 1.0f / (e0 + e1);
        s.prob[j * 2 + 0] = e0 * inv;
        s.prob[j * 2 + 1] = e1 * inv;
    }
    if (tid < MT) {
        const float* bp = tb + ((size_t)f * MT + tid) * 4;
        float cx = bp[0], cy = bp[1], w = bp[2], h = bp[3];
        s.tcx[tid * 4 + 0] = cx; s.tcx[tid * 4 + 1] = cy;
        s.tcx[tid * 4 + 2] = w;  s.tcx[tid * 4 + 3] = h;
        float x0 = cx - 0.5f * w, y0 = cy - 0.5f * h;
        float x1 = cx + 0.5f * w, y1 = cy + 0.5f * h;
        s.txy[tid * 5 + 0] = x0; s.txy[tid * 5 + 1] = y0;
        s.txy[tid * 5 + 2] = x1; s.txy[tid * 5 + 3] = y1;
        s.txy[tid * 5 + 4] = (x1 - x0) * (y1 - y0);
        s.tlab[tid] = tlabels[f * MT + tid];
    }
    __syncthreads();

    // ---------------- Phase 2: cost matrix [MT x NP] ------------------------
    for (int e = tid; e < MT * NP; e += 128) {
        int t = e / NP;
        int j = e - t * NP;
        float l1s = fabsf(s.pcx[j*4+0] - s.tcx[t*4+0])
                  + fabsf(s.pcx[j*4+1] - s.tcx[t*4+1])
                  + fabsf(s.pcx[j*4+2] - s.tcx[t*4+2])
                  + fabsf(s.pcx[j*4+3] - s.tcx[t*4+3]);
        float g = giou_f(s.pxy[j*5+0], s.pxy[j*5+1], s.pxy[j*5+2], s.pxy[j*5+3], s.pxy[j*5+4],
                         s.txy[t*5+0], s.txy[t*5+1], s.txy[t*5+2], s.txy[t*5+3], s.txy[t*5+4]);
        float cc = -s.prob[j * 2 + s.tlab[t]];
        s.cost[t * NP + j] = W_CLS * cc + W_BBOX * l1s + W_GIOU * (-g);
    }
    __syncthreads();

    // ---------------- Phase 3: Hungarian (warp 0), register-resident --------
    // Exact round-7 state evolution (scipy rectangular_lsap, u=v=0 init,
    // every row solved by shortest augmenting path). Mechanics only changed:
    //  - REDUX-based argmin with packed (¬free, j, row4col) key
    //  - register-local u update via mv_scan identity
    // Lane L owns columns j = k*32 + L (k = 0..NL-1, valid while j < NP).
    if (wid == 0) {
        const float INF = FLT_MAX;
        float v_[NL], spc[NL];
        int   pathr[NL], r4c[NL];
        unsigned invmask = 0;
        #pragma unroll
        for (int k = 0; k < NL; k++) {
            int j = k * 32 + lane;
            if (j >= NP) invmask |= 1u << k;
            v_[k] = 0.0f; r4c[k] = -1; pathr[k] = 0;
        }
        float u_own   = 0.0f;   // lane r owns u[r]
        int   c4r_own = -1;     // lane r owns col4row[r]

        for (int cur = 0; cur < MT; cur++) {
            unsigned SC  = invmask;   // scanned-column mask, per lane
            unsigned SRm = 0;         // scanned-row mask, uniform
            #pragma unroll
            for (int k = 0; k < NL; k++) spc[k] = INF;
            float minVal  = 0.0f;
            float mv_scan = 0.0f;     // minVal at the time this lane's row was scanned
            int i = cur;
            int sink = -1;

            while (sink < 0) {
                if (lane == i) mv_scan = minVal;
                SRm |= 1u << i;
                float u_i = __shfl_sync(FULL, u_own, i);
                const float* crow = s.cost + i * NP + lane;

                // hoist the 10 LDS for MLP (OOB slots read in-struct garbage,
                // excluded via SC/invmask below)
                float c_[NL];
                #pragma unroll
                for (int k = 0; k < NL; k++) c_[k] = crow[k * 32];

                float best = INF; int bestkey = 0x7FFFFFFF;
                #pragma unroll
                for (int k = 0; k < NL; k++) {
                    if (!((SC >> k) & 1)) {
                        float r = minVal + c_[k] - u_i - v_[k];
                        if (r < spc[k]) { spc[k] = r; pathr[k] = i; }
                        float sv = spc[k];
                        int rrow = r4c[k];
                        int fr   = (rrow < 0);
                        // key: (¬free)<<14 | j<<5 | row4col; row bits are a
                        // function of j so they never influence selection
                        int key = ((!fr) << 14) | ((k * 32 + lane) << 5)
                                | (fr ? 0 : rrow);
                        if (sv < best || (sv == best && key < bestkey)) {
                            best = sv; bestkey = key;
                        }
                    }
                }
                if (best == 0.0f) best = 0.0f;   // normalize -0 -> +0 for fmap
                unsigned m1 = fmap(best);
                unsigned g  = __reduce_min_sync(FULL, m1);
                unsigned k2 = (m1 == g) ? (unsigned)bestkey : 0xFFFFFFFFu;
                unsigned gk = __reduce_min_sync(FULL, k2);
                minVal = funmap(g);

                int bj   = (int)((gk >> 5) & 511u);
                int bfr  = !((gk >> 14) & 1u);
                int brow = (int)(gk & 31u);
                int owner = bj & 31, slot = bj >> 5;
                if (lane == owner) SC |= 1u << slot;
                if (bfr) sink = bj;
                else     i = brow;
            }

            // Dual updates — all register-local:
            // scanned row i entered the tree at value mv_scan == spc[col4row[i]]
            if ((SRm >> lane) & 1) u_own += minVal - mv_scan;
            #pragma unroll
            for (int k = 0; k < NL; k++) {
                if (((SC >> k) & 1) && !((invmask >> k) & 1))
                    v_[k] -= minVal - spc[k];
            }

            // Augment along the path
            int j = sink;
            for (;;) {
                int slot2 = j >> 5, own2 = j & 31;
                int pv = __shfl_sync(FULL, sel10i(pathr, slot2), own2);
                if (lane == own2) set10i(r4c, slot2, pv);
                int jn = __shfl_sync(FULL, c4r_own, pv);
                if (lane == pv) c4r_own = j;
                if (pv == cur) break;
                j = jn;
            }
        }
        s.col4row[lane] = c4r_own;
    }
    __syncthreads();

    // ---------------- Phase 4: losses ---------------------------------------
    if (tid < MT) {
        int k = s.col4row[tid];
        float l1s = fabsf(s.pcx[k*4+0] - s.tcx[tid*4+0])
                  + fabsf(s.pcx[k*4+1] - s.tcx[tid*4+1])
                  + fabsf(s.pcx[k*4+2] - s.tcx[tid*4+2])
                  + fabsf(s.pcx[k*4+3] - s.tcx[tid*4+3]);
        s.s_l1[tid] = (double)l1s;
        float g = giou_f(s.pxy[k*5+0], s.pxy[k*5+1], s.pxy[k*5+2], s.pxy[k*5+3], s.pxy[k*5+4],
                         s.txy[tid*5+0], s.txy[tid*5+1], s.txy[tid*5+2], s.txy[tid*5+3], s.txy[tid*5+4]);
        s.s_g[tid] = (double)g;
    }

    // ID cross-entropy: one warp per 8 targets, 512-wide logsumexp
    for (int t = wid * 8; t < wid * 8 + 8; t++) {
        int k = s.col4row[t];
        const float* row = il + ((size_t)f * NP + k) * KD;
        float vals[16];
        #pragma unroll
        for (int c = 0; c < 16; c++) vals[c] = row[lane + 32 * c];
        float mx = vals[0];
        #pragma unroll
        for (int c = 1; c < 16; c++) mx = fmaxf(mx, vals[c]);
        for (int off = 16; off; off >>= 1)
            mx = fmaxf(mx, __shfl_xor_sync(0xffffffffu, mx, off));
        float se = 0.0f;
        #pragma unroll
        for (int c = 0; c < 16; c++) se += expf(vals[c] - mx);
        for (int off = 16; off; off >>= 1)
            se += __shfl_xor_sync(0xffffffffu, se, off);
        if (lane == 0) {
            int tg = tids[f * MT + t];
            float lse = mx + logf(se);
            s.s_nll[t] = (double)(lse - row[tg]);
        }
    }
    __syncthreads();

    if (tid == 0) {
        double a = 0.0, b = 0.0, c = 0.0;
        for (int t = 0; t < MT; t++) { a += s.s_l1[t]; b += s.s_g[t]; c += s.s_nll[t]; }
        g_partial[f * 3 + 0] = a;
        g_partial[f * 3 + 1] = b;
        g_partial[f * 3 + 2] = c;
        __threadfence();
        unsigned t = atomicAdd(&g_done, 1u);
        s.lastflag = (t == FR - 1);
    }
    __syncthreads();

    // ---------------- Fused finalize: last CTA reduces all frames -----------
    if (s.lastflag && wid == 0) {
        double a = 0.0, b = 0.0, c = 0.0;
        for (int fr = lane; fr < FR; fr += 32) {
            a += __ldcg(&g_partial[fr * 3 + 0]);
            b += __ldcg(&g_partial[fr * 3 + 1]);
            c += __ldcg(&g_partial[fr * 3 + 2]);
        }
        #pragma unroll
        for (int off = 16; off; off >>= 1) {
            a += __shfl_down_sync(0xffffffffu, a, off);
            b += __shfl_down_sync(0xffffffffu, b, off);
            c += __shfl_down_sync(0xffffffffu, c, off);
        }
        if (lane == 0) {
            double loss_l1   = a / (double)(FR * MT * 4);
            double loss_giou = 1.0 - b / (double)(FR * MT);
            double loss_id   = c / (double)(FR * MT);
            double loss = 5.0 * loss_l1 + 2.0 * loss_giou + 1.0 * loss_id; // cls stub = 0
            out[0] = (float)loss;
            out[1] = 0.0f;
            out[2] = (float)loss_l1;
            out[3] = (float)loss_giou;
            out[4] = (float)loss_id;
            g_done = 0;   // reset for next graph replay
        }
    }
}

extern "C" void kernel_launch(void* const* d_in, const int* in_sizes, int n_in,
                              void* d_out, int out_size)
{
    const float* pl  = (const float*)d_in[0];
    const float* pb  = (const float*)d_in[1];
    const float* il  = (const float*)d_in[2];
    const int*   tl  = (const int*)  d_in[3];
    const float* tb  = (const float*)d_in[4];
    const int*   tid = (const int*)  d_in[5];

    size_t smem = sizeof(SMem);
    cudaFuncSetAttribute(motip_frame_kernel,
                         cudaFuncAttributeMaxDynamicSharedMemorySize, (int)smem);
    motip_frame_kernel<<<FR, 128, smem>>>(pl, pb, il, tl, tb, tid, (float*)d_out);
}